// round 10
// baseline (speedup 1.0000x reference)
#include <cuda_runtime.h>
#include <math.h>
#include <stdint.h>

#define BB   32
#define SEQ  197
#define DIM  768
#define NHD  12
#define HD   64
#define NL   12
#define NCLS 1000
#define MLPD 3072
#define NTOK (BB*SEQ)     // 6304
#define NPAT 196
#define MT128 ((NTOK+127)/128)   // 50 M-tiles of 128

// -------------------- scratch (device globals; no allocation allowed) -----
__device__ float g_X[NTOK*DIM];
__device__ float g_H[NTOK*DIM];
__device__ float g_A[BB*NPAT*DIM];
__device__ float g_Q[NTOK*DIM];
__device__ float g_K[NTOK*DIM];
__device__ float g_V[NTOK*DIM];
__device__ float g_U[(size_t)NTOK*MLPD];

// -------------------- patchify: (B,C,224,224) -> (B*196, 768) ------------
__global__ void patchify_kernel(const float* __restrict__ img)
{
    int idx = blockIdx.x*256 + threadIdx.x;
    const int total = BB*NPAT*DIM;
    if (idx >= total) return;
    int f = idx % DIM;
    int p = (idx / DIM) % NPAT;
    int b = idx / (DIM*NPAT);
    int c = f >> 8;
    int rem = f & 255;
    int i = rem >> 4;
    int j = rem & 15;
    int pr = p / 14, pc = p % 14;
    g_A[idx] = img[(((size_t)b*3 + c)*224 + (pr*16+i))*224 + (pc*16+j)];
}

// -------------------- assemble tokens: cls + embed + pos -> X ------------
__global__ void assemble_kernel(const float* __restrict__ cls,
                                const float* __restrict__ pos)
{
    int idx = blockIdx.x*256 + threadIdx.x;
    if (idx >= NTOK*DIM) return;
    int d = idx % DIM;
    int s = (idx / DIM) % SEQ;
    int b = idx / (DIM*SEQ);
    float v = (s == 0) ? cls[d] : g_H[((size_t)b*NPAT + (s-1))*DIM + d];
    g_X[idx] = v + pos[s*DIM + d];
}

// ==================== TF32x3 tensor-core GEMM =============================
// C-tile 128x64 per block, 256 threads (8 warps in 4x2), warp tile 32x32.
// A: MxK row-major (lda), B: KxN row-major (ldb).
// Precision: split each operand into tf32 hi + tf32 lo, do hi*hi+hi*lo+lo*hi.
// EPI 0: C = acc + bias ; 1: C = gelu(acc+bias) ; 2: C += acc + bias

#define BM 128
#define BN 64
#define BKK 32

__device__ __forceinline__ void split_tf32(float x, uint32_t& hi, uint32_t& lo)
{
    uint32_t h;
    asm("cvt.rna.tf32.f32 %0, %1;" : "=r"(h) : "f"(x));
    float r = x - __uint_as_float(h);
    uint32_t l;
    asm("cvt.rna.tf32.f32 %0, %1;" : "=r"(l) : "f"(r));
    hi = h; lo = l;
}

__device__ __forceinline__ void mma_tf32(float* cc, const uint32_t* a, const uint32_t* b)
{
    asm volatile(
        "mma.sync.aligned.m16n8k8.row.col.f32.tf32.tf32.f32 "
        "{%0,%1,%2,%3}, {%4,%5,%6,%7}, {%8,%9}, {%0,%1,%2,%3};\n"
        : "+f"(cc[0]), "+f"(cc[1]), "+f"(cc[2]), "+f"(cc[3])
        : "r"(a[0]), "r"(a[1]), "r"(a[2]), "r"(a[3]),
          "r"(b[0]), "r"(b[1]));
}

template<int EPI>
__device__ __forceinline__ void mma_gemm_tile(
    const float* __restrict__ A, int lda,
    const float* __restrict__ Bm, int ldb,
    const float* __restrict__ bias,
    float* __restrict__ C, int ldc,
    int M, int K, int m0, int n0)
{
    __shared__ float As[BM][BKK+4];   // stride 36: frag reads conflict-free
    __shared__ float Bs[BKK][BN+8];   // stride 72: frag reads conflict-free

    int tid  = threadIdx.x;
    int lane = tid & 31, wid = tid >> 5;
    int warpM = wid >> 1, warpN = wid & 1;
    int g = lane >> 2, c = lane & 3;

    float acc[2][4][4];
#pragma unroll
    for (int mt = 0; mt < 2; mt++)
#pragma unroll
        for (int nt = 0; nt < 4; nt++)
#pragma unroll
            for (int i = 0; i < 4; i++) acc[mt][nt][i] = 0.f;

    for (int k0 = 0; k0 < K; k0 += BKK) {
        // load A tile 128x32 (4 float4 / thread)
#pragma unroll
        for (int i = 0; i < 4; i++) {
            int idx = tid + i*256;       // 0..1023
            int row = idx >> 3, c4 = idx & 7;
            int gm  = m0 + row;
            float4 v = (gm < M)
                ? *reinterpret_cast<const float4*>(&A[(size_t)gm*lda + k0 + c4*4])
                : make_float4(0.f, 0.f, 0.f, 0.f);
            *reinterpret_cast<float4*>(&As[row][c4*4]) = v;
        }
        // load B tile 32x64 (2 float4 / thread)
#pragma unroll
        for (int i = 0; i < 2; i++) {
            int idx = tid + i*256;       // 0..511
            int row = idx >> 4, c4 = idx & 15;
            float4 v = *reinterpret_cast<const float4*>(
                &Bm[(size_t)(k0+row)*ldb + n0 + c4*4]);
            *reinterpret_cast<float4*>(&Bs[row][c4*4]) = v;
        }
        __syncthreads();

#pragma unroll
        for (int kk = 0; kk < BKK; kk += 8) {
            uint32_t ah[2][4], al[2][4];
#pragma unroll
            for (int mt = 0; mt < 2; mt++) {
                int r = warpM*32 + mt*16 + g;
                float a0 = As[r  ][kk + c];
                float a1 = As[r+8][kk + c];
                float a2 = As[r  ][kk + c + 4];
                float a3 = As[r+8][kk + c + 4];
                split_tf32(a0, ah[mt][0], al[mt][0]);
                split_tf32(a1, ah[mt][1], al[mt][1]);
                split_tf32(a2, ah[mt][2], al[mt][2]);
                split_tf32(a3, ah[mt][3], al[mt][3]);
            }
            uint32_t bh[4][2], bl[4][2];
#pragma unroll
            for (int nt = 0; nt < 4; nt++) {
                int ncol = warpN*32 + nt*8 + g;
                float b0 = Bs[kk + c    ][ncol];
                float b1 = Bs[kk + c + 4][ncol];
                split_tf32(b0, bh[nt][0], bl[nt][0]);
                split_tf32(b1, bh[nt][1], bl[nt][1]);
            }
#pragma unroll
            for (int mt = 0; mt < 2; mt++)
#pragma unroll
                for (int nt = 0; nt < 4; nt++) {
                    mma_tf32(acc[mt][nt], ah[mt], bl[nt]);
                    mma_tf32(acc[mt][nt], al[mt], bh[nt]);
                    mma_tf32(acc[mt][nt], ah[mt], bh[nt]);
                }
        }
        __syncthreads();
    }

    // epilogue
#pragma unroll
    for (int mt = 0; mt < 2; mt++) {
#pragma unroll
        for (int nt = 0; nt < 4; nt++) {
            int r0  = m0 + warpM*32 + mt*16 + g;
            int col = n0 + warpN*32 + nt*8 + 2*c;
#pragma unroll
            for (int half = 0; half < 2; half++) {
                int gm = r0 + half*8;
                if (gm >= M) continue;
#pragma unroll
                for (int jj = 0; jj < 2; jj++) {
                    int gn = col + jj;
                    float v = acc[mt][nt][half*2 + jj] + bias[gn];
                    float* cp = &C[(size_t)gm*ldc + gn];
                    if (EPI == 1) v = 0.5f*v*(1.f + erff(v*0.70710678118654752f));
                    if (EPI == 2) v += *cp;
                    *cp = v;
                }
            }
        }
    }
}

template<int EPI>
__global__ __launch_bounds__(256) void mma_gemm_kernel(
    const float* __restrict__ A, int lda,
    const float* __restrict__ Bm, int ldb,
    const float* __restrict__ bias,
    float* __restrict__ C, int ldc, int M, int K)
{
    mma_gemm_tile<EPI>(A, lda, Bm, ldb, bias, C, ldc, M, K,
                       blockIdx.y*BM, blockIdx.x*BN);
}

// per-head QKV via the same MMA tile. grid: (1, Mtiles128, 36 = 12 heads x 3)
__global__ __launch_bounds__(256) void qkv_mma_kernel(
    const float* __restrict__ Wq, const float* __restrict__ bq,
    const float* __restrict__ Wk, const float* __restrict__ bk,
    const float* __restrict__ Wv, const float* __restrict__ bv,
    int layer)
{
    int z = blockIdx.z;
    int h = z % NHD, t = z / NHD;
    const float* W; const float* bi; float* C;
    if (t == 0)      { W = Wq; bi = bq; C = g_Q; }
    else if (t == 1) { W = Wk; bi = bk; C = g_K; }
    else             { W = Wv; bi = bv; C = g_V; }
    size_t off = (size_t)layer*NHD + h;
    mma_gemm_tile<0>(g_H + h*HD, DIM,
                     W + off*HD*HD, HD,
                     bi + off*HD,
                     C + h*HD, DIM,
                     NTOK, HD, blockIdx.y*BM, 0);
}

// -------------------- layernorm ------------------------------------------
__global__ __launch_bounds__(256) void ln_kernel(
    const float* __restrict__ X, float* __restrict__ H,
    const float* __restrict__ gw, const float* __restrict__ bw)
{
    __shared__ float rs[8], rq[8];
    int row = blockIdx.x, tid = threadIdx.x;
    int lane = tid & 31, wid = tid >> 5;
    const float* x = X + (size_t)row*DIM;
    float v0 = x[tid], v1 = x[tid+256], v2 = x[tid+512];
    float s = v0+v1+v2;
    float q = v0*v0 + v1*v1 + v2*v2;
#pragma unroll
    for (int o = 16; o; o >>= 1) {
        s += __shfl_xor_sync(0xffffffffu, s, o);
        q += __shfl_xor_sync(0xffffffffu, q, o);
    }
    if (lane == 0) { rs[wid] = s; rq[wid] = q; }
    __syncthreads();
    if (tid == 0) {
        float ts = 0.f, tq = 0.f;
        for (int w = 0; w < 8; w++) { ts += rs[w]; tq += rq[w]; }
        rs[0] = ts; rq[0] = tq;
    }
    __syncthreads();
    float mean = rs[0]*(1.0f/DIM);
    float var  = rq[0]*(1.0f/DIM) - mean*mean;
    float inv  = rsqrtf(var + 1e-5f);
    float* hrow = H + (size_t)row*DIM;
    hrow[tid]     = (v0-mean)*inv*gw[tid]     + bw[tid];
    hrow[tid+256] = (v1-mean)*inv*gw[tid+256] + bw[tid+256];
    hrow[tid+512] = (v2-mean)*inv*gw[tid+512] + bw[tid+512];
}

// -------------------- attention (one block per (b,h)) --------------------
#define ATTN_SMEM_FLOATS (2*SEQ*HD + HD + SEQ + 8)
#define ATTN_SMEM_BYTES  (ATTN_SMEM_FLOATS*4)

__global__ __launch_bounds__(128) void attn_kernel(
    const float* __restrict__ Q, const float* __restrict__ K,
    const float* __restrict__ V, float* __restrict__ X)
{
    extern __shared__ float sm[];
    float* Ks  = sm;
    float* Vs  = Ks + SEQ*HD;
    float* qs  = Vs + SEQ*HD;
    float* ps  = qs + HD;
    float* red = ps + SEQ;

    int bh = blockIdx.x;
    int b = bh / NHD, h = bh % NHD;
    int tid = threadIdx.x;
    int lane = tid & 31, wid = tid >> 5;
    size_t base = (size_t)b*SEQ*DIM + (size_t)h*HD;

    for (int idx = tid; idx < SEQ*HD; idx += 128) {
        int t = idx >> 6, e = idx & 63;
        Ks[idx] = K[base + (size_t)t*DIM + e];
        Vs[idx] = V[base + (size_t)t*DIM + e];
    }
    __syncthreads();

    int rot = tid & 63;
    for (int s = 0; s < SEQ; s++) {
        if (tid < HD) qs[tid] = Q[base + (size_t)s*DIM + tid];
        __syncthreads();

        float lm = -1e30f;
        for (int j = tid; j < SEQ; j += 128) {
            float d = 0.f;
            const float* kr = &Ks[j*HD];
#pragma unroll
            for (int e = 0; e < HD; e++) {
                int ee = (e + rot) & 63;
                d = fmaf(qs[ee], kr[ee], d);
            }
            d *= 0.125f;
            ps[j] = d;
            lm = fmaxf(lm, d);
        }
#pragma unroll
        for (int o = 16; o; o >>= 1) lm = fmaxf(lm, __shfl_xor_sync(0xffffffffu, lm, o));
        if (lane == 0) red[wid] = lm;
        __syncthreads();
        if (tid == 0) {
            float m = fmaxf(fmaxf(red[0], red[1]), fmaxf(red[2], red[3]));
            red[4] = m;
        }
        __syncthreads();
        float mx = red[4];

        float ls = 0.f;
        for (int j = tid; j < SEQ; j += 128) {
            float e = expf(ps[j] - mx);
            ps[j] = e;
            ls += e;
        }
#pragma unroll
        for (int o = 16; o; o >>= 1) ls += __shfl_xor_sync(0xffffffffu, ls, o);
        __syncthreads();
        if (lane == 0) red[wid] = ls;
        __syncthreads();
        if (tid == 0) red[5] = red[0] + red[1] + red[2] + red[3];
        __syncthreads();
        float inv = 1.f / red[5];

        if (tid < HD) {
            float acc = 0.f;
            for (int t = 0; t < SEQ; t++)
                acc = fmaf(ps[t], Vs[t*HD + tid], acc);
            X[base + (size_t)s*DIM + tid] += acc * inv;
        }
        __syncthreads();
    }
}

// -------------------- classifier head + softmax --------------------------
__global__ __launch_bounds__(256) void head_kernel(
    const float* __restrict__ X, const float* __restrict__ Wh,
    const float* __restrict__ bh, float* __restrict__ out)
{
    __shared__ float xr[DIM];
    __shared__ float lg[NCLS];
    __shared__ float red[8];
    int b = blockIdx.x, tid = threadIdx.x;
    int lane = tid & 31, wid = tid >> 5;

    for (int d = tid; d < DIM; d += 256) xr[d] = X[(size_t)b*SEQ*DIM + d];
    __syncthreads();

    for (int n = tid; n < NCLS; n += 256) {
        float a = bh[n];
        for (int k = 0; k < DIM; k++)
            a = fmaf(xr[k], Wh[(size_t)k*NCLS + n], a);
        lg[n] = a;
    }
    __syncthreads();

    float lm = -1e30f;
    for (int n = tid; n < NCLS; n += 256) lm = fmaxf(lm, lg[n]);
#pragma unroll
    for (int o = 16; o; o >>= 1) lm = fmaxf(lm, __shfl_xor_sync(0xffffffffu, lm, o));
    if (lane == 0) red[wid] = lm;
    __syncthreads();
    if (tid == 0) {
        float m = red[0];
        for (int w = 1; w < 8; w++) m = fmaxf(m, red[w]);
        red[0] = m;
    }
    __syncthreads();
    float mx = red[0];

    float ls = 0.f;
    for (int n = tid; n < NCLS; n += 256) {
        float e = expf(lg[n] - mx);
        lg[n] = e;
        ls += e;
    }
#pragma unroll
    for (int o = 16; o; o >>= 1) ls += __shfl_xor_sync(0xffffffffu, ls, o);
    __syncthreads();
    if (lane == 0) red[wid] = ls;
    __syncthreads();
    if (tid == 0) {
        float s2 = 0.f;
        for (int w = 0; w < 8; w++) s2 += red[w];
        red[0] = s2;
    }
    __syncthreads();
    float inv = 1.f / red[0];
    for (int n = tid; n < NCLS; n += 256)
        out[(size_t)b*NCLS + n] = lg[n]*inv;
}

// -------------------- launch ---------------------------------------------
extern "C" void kernel_launch(void* const* d_in, const int* in_sizes, int n_in,
                              void* d_out, int out_size)
{
    (void)in_sizes; (void)n_in; (void)out_size;
    const float* images = (const float*)d_in[0];
    const float* Wp     = (const float*)d_in[1];
    const float* bp     = (const float*)d_in[2];
    const float* cls    = (const float*)d_in[3];
    const float* pos    = (const float*)d_in[4];
    const float* ln1_g  = (const float*)d_in[5];
    const float* ln1_b  = (const float*)d_in[6];
    const float* Wq     = (const float*)d_in[7];
    const float* bq     = (const float*)d_in[8];
    const float* Wk     = (const float*)d_in[9];
    const float* bk     = (const float*)d_in[10];
    const float* Wv     = (const float*)d_in[11];
    const float* bv     = (const float*)d_in[12];
    const float* ln2_g  = (const float*)d_in[13];
    const float* ln2_b  = (const float*)d_in[14];
    const float* W1     = (const float*)d_in[15];
    const float* b1     = (const float*)d_in[16];
    const float* W2     = (const float*)d_in[17];
    const float* b2     = (const float*)d_in[18];
    const float* Wh     = (const float*)d_in[19];
    const float* bh     = (const float*)d_in[20];
    float* out = (float*)d_out;

    float *pA, *pH, *pX, *pQ, *pK, *pV, *pU;
    cudaGetSymbolAddress((void**)&pA, g_A);
    cudaGetSymbolAddress((void**)&pH, g_H);
    cudaGetSymbolAddress((void**)&pX, g_X);
    cudaGetSymbolAddress((void**)&pQ, g_Q);
    cudaGetSymbolAddress((void**)&pK, g_K);
    cudaGetSymbolAddress((void**)&pV, g_V);
    cudaGetSymbolAddress((void**)&pU, g_U);

    cudaFuncSetAttribute(attn_kernel,
                         cudaFuncAttributeMaxDynamicSharedMemorySize,
                         ATTN_SMEM_BYTES);

    // Patch embed: (6272 x 768) @ (768 x 768)
    patchify_kernel<<<(BB*NPAT*DIM + 255)/256, 256>>>(images);
    mma_gemm_kernel<0><<<dim3(DIM/BN, (BB*NPAT+BM-1)/BM), 256>>>(
        pA, DIM, Wp, DIM, bp, pH, DIM, BB*NPAT, DIM);
    assemble_kernel<<<(NTOK*DIM + 255)/256, 256>>>(cls, pos);

    for (int l = 0; l < NL; l++) {
        ln_kernel<<<NTOK, 256>>>(pX, pH, ln1_g + l*DIM, ln1_b + l*DIM);
        qkv_mma_kernel<<<dim3(1, MT128, NHD*3), 256>>>(Wq, bq, Wk, bk, Wv, bv, l);
        attn_kernel<<<BB*NHD, 128, ATTN_SMEM_BYTES>>>(pQ, pK, pV, pX);
        ln_kernel<<<NTOK, 256>>>(pX, pH, ln2_g + l*DIM, ln2_b + l*DIM);
        mma_gemm_kernel<1><<<dim3(MLPD/BN, MT128), 256>>>(
            pH, DIM, W1 + (size_t)l*DIM*MLPD, MLPD, b1 + (size_t)l*MLPD,
            pU, MLPD, NTOK, DIM);
        mma_gemm_kernel<2><<<dim3(DIM/BN, MT128), 256>>>(
            pU, MLPD, W2 + (size_t)l*MLPD*DIM, DIM, b2 + (size_t)l*DIM,
            pX, DIM, NTOK, MLPD);
    }

    head_kernel<<<BB, 256>>>(pX, Wh, bh, out);
}

// round 11
// speedup vs baseline: 1.0021x; 1.0021x over previous
#include <cuda_runtime.h>
#include <math.h>
#include <stdint.h>

#define BB   32
#define SEQ  197
#define DIM  768
#define NHD  12
#define HD   64
#define NL   12
#define NCLS 1000
#define MLPD 3072
#define NTOK (BB*SEQ)     // 6304
#define NPAT 196
#define MT128 ((NTOK+127)/128)   // 50 M-tiles of 128

// -------------------- scratch (device globals; no allocation allowed) -----
__device__ float g_X[NTOK*DIM];
__device__ float g_H[NTOK*DIM];
__device__ float g_A[BB*NPAT*DIM];
__device__ float g_Q[NTOK*DIM];
__device__ float g_K[NTOK*DIM];
__device__ float g_V[NTOK*DIM];
__device__ float g_U[(size_t)NTOK*MLPD];

// -------------------- patchify: (B,C,224,224) -> (B*196, 768) ------------
__global__ void patchify_kernel(const float* __restrict__ img)
{
    int idx = blockIdx.x*256 + threadIdx.x;
    const int total = BB*NPAT*DIM;
    if (idx >= total) return;
    int f = idx % DIM;
    int p = (idx / DIM) % NPAT;
    int b = idx / (DIM*NPAT);
    int c = f >> 8;
    int rem = f & 255;
    int i = rem >> 4;
    int j = rem & 15;
    int pr = p / 14, pc = p % 14;
    g_A[idx] = img[(((size_t)b*3 + c)*224 + (pr*16+i))*224 + (pc*16+j)];
}

// -------------------- assemble tokens: cls + embed + pos -> X ------------
__global__ void assemble_kernel(const float* __restrict__ cls,
                                const float* __restrict__ pos)
{
    int idx = blockIdx.x*256 + threadIdx.x;
    if (idx >= NTOK*DIM) return;
    int d = idx % DIM;
    int s = (idx / DIM) % SEQ;
    int b = idx / (DIM*SEQ);
    float v = (s == 0) ? cls[d] : g_H[((size_t)b*NPAT + (s-1))*DIM + d];
    g_X[idx] = v + pos[s*DIM + d];
}

// ==================== TF32x3 tensor-core GEMM =============================
// C-tile 128x64 per block, 256 threads (8 warps in 4x2), warp tile 32x32.
// A: MxK row-major (lda), B: KxN row-major (ldb).
// Precision: split each operand into tf32 hi + tf32 lo, do hi*hi+hi*lo+lo*hi.
// EPI 0: C = acc + bias ; 1: C = gelu(acc+bias) ; 2: C += acc + bias

#define BM 128
#define BN 64
#define BKK 32

__device__ __forceinline__ void split_tf32(float x, uint32_t& hi, uint32_t& lo)
{
    uint32_t h;
    asm("cvt.rna.tf32.f32 %0, %1;" : "=r"(h) : "f"(x));
    float r = x - __uint_as_float(h);
    uint32_t l;
    asm("cvt.rna.tf32.f32 %0, %1;" : "=r"(l) : "f"(r));
    hi = h; lo = l;
}

__device__ __forceinline__ void mma_tf32(float* cc, const uint32_t* a, const uint32_t* b)
{
    asm volatile(
        "mma.sync.aligned.m16n8k8.row.col.f32.tf32.tf32.f32 "
        "{%0,%1,%2,%3}, {%4,%5,%6,%7}, {%8,%9}, {%0,%1,%2,%3};\n"
        : "+f"(cc[0]), "+f"(cc[1]), "+f"(cc[2]), "+f"(cc[3])
        : "r"(a[0]), "r"(a[1]), "r"(a[2]), "r"(a[3]),
          "r"(b[0]), "r"(b[1]));
}

template<int EPI>
__device__ __forceinline__ void mma_gemm_tile(
    const float* __restrict__ A, int lda,
    const float* __restrict__ Bm, int ldb,
    const float* __restrict__ bias,
    float* __restrict__ C, int ldc,
    int M, int K, int m0, int n0)
{
    __shared__ float As[BM][BKK+4];   // stride 36: frag reads conflict-free
    __shared__ float Bs[BKK][BN+8];   // stride 72: frag reads conflict-free

    int tid  = threadIdx.x;
    int lane = tid & 31, wid = tid >> 5;
    int warpM = wid >> 1, warpN = wid & 1;
    int g = lane >> 2, c = lane & 3;

    float acc[2][4][4];
#pragma unroll
    for (int mt = 0; mt < 2; mt++)
#pragma unroll
        for (int nt = 0; nt < 4; nt++)
#pragma unroll
            for (int i = 0; i < 4; i++) acc[mt][nt][i] = 0.f;

    for (int k0 = 0; k0 < K; k0 += BKK) {
        // load A tile 128x32 (4 float4 / thread)
#pragma unroll
        for (int i = 0; i < 4; i++) {
            int idx = tid + i*256;       // 0..1023
            int row = idx >> 3, c4 = idx & 7;
            int gm  = m0 + row;
            float4 v = (gm < M)
                ? *reinterpret_cast<const float4*>(&A[(size_t)gm*lda + k0 + c4*4])
                : make_float4(0.f, 0.f, 0.f, 0.f);
            *reinterpret_cast<float4*>(&As[row][c4*4]) = v;
        }
        // load B tile 32x64 (2 float4 / thread)
#pragma unroll
        for (int i = 0; i < 2; i++) {
            int idx = tid + i*256;       // 0..511
            int row = idx >> 4, c4 = idx & 15;
            float4 v = *reinterpret_cast<const float4*>(
                &Bm[(size_t)(k0+row)*ldb + n0 + c4*4]);
            *reinterpret_cast<float4*>(&Bs[row][c4*4]) = v;
        }
        __syncthreads();

#pragma unroll
        for (int kk = 0; kk < BKK; kk += 8) {
            uint32_t ah[2][4], al[2][4];
#pragma unroll
            for (int mt = 0; mt < 2; mt++) {
                int r = warpM*32 + mt*16 + g;
                float a0 = As[r  ][kk + c];
                float a1 = As[r+8][kk + c];
                float a2 = As[r  ][kk + c + 4];
                float a3 = As[r+8][kk + c + 4];
                split_tf32(a0, ah[mt][0], al[mt][0]);
                split_tf32(a1, ah[mt][1], al[mt][1]);
                split_tf32(a2, ah[mt][2], al[mt][2]);
                split_tf32(a3, ah[mt][3], al[mt][3]);
            }
            uint32_t bh[4][2], bl[4][2];
#pragma unroll
            for (int nt = 0; nt < 4; nt++) {
                int ncol = warpN*32 + nt*8 + g;
                float b0 = Bs[kk + c    ][ncol];
                float b1 = Bs[kk + c + 4][ncol];
                split_tf32(b0, bh[nt][0], bl[nt][0]);
                split_tf32(b1, bh[nt][1], bl[nt][1]);
            }
#pragma unroll
            for (int mt = 0; mt < 2; mt++)
#pragma unroll
                for (int nt = 0; nt < 4; nt++) {
                    mma_tf32(acc[mt][nt], ah[mt], bl[nt]);
                    mma_tf32(acc[mt][nt], al[mt], bh[nt]);
                    mma_tf32(acc[mt][nt], ah[mt], bh[nt]);
                }
        }
        __syncthreads();
    }

    // epilogue
#pragma unroll
    for (int mt = 0; mt < 2; mt++) {
#pragma unroll
        for (int nt = 0; nt < 4; nt++) {
            int r0  = m0 + warpM*32 + mt*16 + g;
            int col = n0 + warpN*32 + nt*8 + 2*c;
#pragma unroll
            for (int half = 0; half < 2; half++) {
                int gm = r0 + half*8;
                if (gm >= M) continue;
#pragma unroll
                for (int jj = 0; jj < 2; jj++) {
                    int gn = col + jj;
                    float v = acc[mt][nt][half*2 + jj] + bias[gn];
                    float* cp = &C[(size_t)gm*ldc + gn];
                    if (EPI == 1) v = 0.5f*v*(1.f + erff(v*0.70710678118654752f));
                    if (EPI == 2) v += *cp;
                    *cp = v;
                }
            }
        }
    }
}

template<int EPI>
__global__ __launch_bounds__(256) void mma_gemm_kernel(
    const float* __restrict__ A, int lda,
    const float* __restrict__ Bm, int ldb,
    const float* __restrict__ bias,
    float* __restrict__ C, int ldc, int M, int K)
{
    mma_gemm_tile<EPI>(A, lda, Bm, ldb, bias, C, ldc, M, K,
                       blockIdx.y*BM, blockIdx.x*BN);
}

// per-head QKV via the same MMA tile. grid: (1, Mtiles128, 36 = 12 heads x 3)
__global__ __launch_bounds__(256) void qkv_mma_kernel(
    const float* __restrict__ Wq, const float* __restrict__ bq,
    const float* __restrict__ Wk, const float* __restrict__ bk,
    const float* __restrict__ Wv, const float* __restrict__ bv,
    int layer)
{
    int z = blockIdx.z;
    int h = z % NHD, t = z / NHD;
    const float* W; const float* bi; float* C;
    if (t == 0)      { W = Wq; bi = bq; C = g_Q; }
    else if (t == 1) { W = Wk; bi = bk; C = g_K; }
    else             { W = Wv; bi = bv; C = g_V; }
    size_t off = (size_t)layer*NHD + h;
    mma_gemm_tile<0>(g_H + h*HD, DIM,
                     W + off*HD*HD, HD,
                     bi + off*HD,
                     C + h*HD, DIM,
                     NTOK, HD, blockIdx.y*BM, 0);
}

// -------------------- layernorm ------------------------------------------
__global__ __launch_bounds__(256) void ln_kernel(
    const float* __restrict__ X, float* __restrict__ H,
    const float* __restrict__ gw, const float* __restrict__ bw)
{
    __shared__ float rs[8], rq[8];
    int row = blockIdx.x, tid = threadIdx.x;
    int lane = tid & 31, wid = tid >> 5;
    const float* x = X + (size_t)row*DIM;
    float v0 = x[tid], v1 = x[tid+256], v2 = x[tid+512];
    float s = v0+v1+v2;
    float q = v0*v0 + v1*v1 + v2*v2;
#pragma unroll
    for (int o = 16; o; o >>= 1) {
        s += __shfl_xor_sync(0xffffffffu, s, o);
        q += __shfl_xor_sync(0xffffffffu, q, o);
    }
    if (lane == 0) { rs[wid] = s; rq[wid] = q; }
    __syncthreads();
    if (tid == 0) {
        float ts = 0.f, tq = 0.f;
        for (int w = 0; w < 8; w++) { ts += rs[w]; tq += rq[w]; }
        rs[0] = ts; rq[0] = tq;
    }
    __syncthreads();
    float mean = rs[0]*(1.0f/DIM);
    float var  = rq[0]*(1.0f/DIM) - mean*mean;
    float inv  = rsqrtf(var + 1e-5f);
    float* hrow = H + (size_t)row*DIM;
    hrow[tid]     = (v0-mean)*inv*gw[tid]     + bw[tid];
    hrow[tid+256] = (v1-mean)*inv*gw[tid+256] + bw[tid+256];
    hrow[tid+512] = (v2-mean)*inv*gw[tid+512] + bw[tid+512];
}

// -------------------- attention (one block per (b,h)) --------------------
#define ATTN_SMEM_FLOATS (2*SEQ*HD + HD + SEQ + 8)
#define ATTN_SMEM_BYTES  (ATTN_SMEM_FLOATS*4)

__global__ __launch_bounds__(128) void attn_kernel(
    const float* __restrict__ Q, const float* __restrict__ K,
    const float* __restrict__ V, float* __restrict__ X)
{
    extern __shared__ float sm[];
    float* Ks  = sm;
    float* Vs  = Ks + SEQ*HD;
    float* qs  = Vs + SEQ*HD;
    float* ps  = qs + HD;
    float* red = ps + SEQ;

    int bh = blockIdx.x;
    int b = bh / NHD, h = bh % NHD;
    int tid = threadIdx.x;
    int lane = tid & 31, wid = tid >> 5;
    size_t base = (size_t)b*SEQ*DIM + (size_t)h*HD;

    for (int idx = tid; idx < SEQ*HD; idx += 128) {
        int t = idx >> 6, e = idx & 63;
        Ks[idx] = K[base + (size_t)t*DIM + e];
        Vs[idx] = V[base + (size_t)t*DIM + e];
    }
    __syncthreads();

    int rot = tid & 63;
    for (int s = 0; s < SEQ; s++) {
        if (tid < HD) qs[tid] = Q[base + (size_t)s*DIM + tid];
        __syncthreads();

        float lm = -1e30f;
        for (int j = tid; j < SEQ; j += 128) {
            float d = 0.f;
            const float* kr = &Ks[j*HD];
#pragma unroll
            for (int e = 0; e < HD; e++) {
                int ee = (e + rot) & 63;
                d = fmaf(qs[ee], kr[ee], d);
            }
            d *= 0.125f;
            ps[j] = d;
            lm = fmaxf(lm, d);
        }
#pragma unroll
        for (int o = 16; o; o >>= 1) lm = fmaxf(lm, __shfl_xor_sync(0xffffffffu, lm, o));
        if (lane == 0) red[wid] = lm;
        __syncthreads();
        if (tid == 0) {
            float m = fmaxf(fmaxf(red[0], red[1]), fmaxf(red[2], red[3]));
            red[4] = m;
        }
        __syncthreads();
        float mx = red[4];

        float ls = 0.f;
        for (int j = tid; j < SEQ; j += 128) {
            float e = expf(ps[j] - mx);
            ps[j] = e;
            ls += e;
        }
#pragma unroll
        for (int o = 16; o; o >>= 1) ls += __shfl_xor_sync(0xffffffffu, ls, o);
        __syncthreads();
        if (lane == 0) red[wid] = ls;
        __syncthreads();
        if (tid == 0) red[5] = red[0] + red[1] + red[2] + red[3];
        __syncthreads();
        float inv = 1.f / red[5];

        if (tid < HD) {
            float acc = 0.f;
            for (int t = 0; t < SEQ; t++)
                acc = fmaf(ps[t], Vs[t*HD + tid], acc);
            X[base + (size_t)s*DIM + tid] += acc * inv;
        }
        __syncthreads();
    }
}

// -------------------- classifier head + softmax --------------------------
__global__ __launch_bounds__(256) void head_kernel(
    const float* __restrict__ X, const float* __restrict__ Wh,
    const float* __restrict__ bh, float* __restrict__ out)
{
    __shared__ float xr[DIM];
    __shared__ float lg[NCLS];
    __shared__ float red[8];
    int b = blockIdx.x, tid = threadIdx.x;
    int lane = tid & 31, wid = tid >> 5;

    for (int d = tid; d < DIM; d += 256) xr[d] = X[(size_t)b*SEQ*DIM + d];
    __syncthreads();

    for (int n = tid; n < NCLS; n += 256) {
        float a = bh[n];
        for (int k = 0; k < DIM; k++)
            a = fmaf(xr[k], Wh[(size_t)k*NCLS + n], a);
        lg[n] = a;
    }
    __syncthreads();

    float lm = -1e30f;
    for (int n = tid; n < NCLS; n += 256) lm = fmaxf(lm, lg[n]);
#pragma unroll
    for (int o = 16; o; o >>= 1) lm = fmaxf(lm, __shfl_xor_sync(0xffffffffu, lm, o));
    if (lane == 0) red[wid] = lm;
    __syncthreads();
    if (tid == 0) {
        float m = red[0];
        for (int w = 1; w < 8; w++) m = fmaxf(m, red[w]);
        red[0] = m;
    }
    __syncthreads();
    float mx = red[0];

    float ls = 0.f;
    for (int n = tid; n < NCLS; n += 256) {
        float e = expf(lg[n] - mx);
        lg[n] = e;
        ls += e;
    }
#pragma unroll
    for (int o = 16; o; o >>= 1) ls += __shfl_xor_sync(0xffffffffu, ls, o);
    __syncthreads();
    if (lane == 0) red[wid] = ls;
    __syncthreads();
    if (tid == 0) {
        float s2 = 0.f;
        for (int w = 0; w < 8; w++) s2 += red[w];
        red[0] = s2;
    }
    __syncthreads();
    float inv = 1.f / red[0];
    for (int n = tid; n < NCLS; n += 256)
        out[(size_t)b*NCLS + n] = lg[n]*inv;
}

// -------------------- launch ---------------------------------------------
extern "C" void kernel_launch(void* const* d_in, const int* in_sizes, int n_in,
                              void* d_out, int out_size)
{
    (void)in_sizes; (void)n_in; (void)out_size;
    const float* images = (const float*)d_in[0];
    const float* Wp     = (const float*)d_in[1];
    const float* bp     = (const float*)d_in[2];
    const float* cls    = (const float*)d_in[3];
    const float* pos    = (const float*)d_in[4];
    const float* ln1_g  = (const float*)d_in[5];
    const float* ln1_b  = (const float*)d_in[6];
    const float* Wq     = (const float*)d_in[7];
    const float* bq     = (const float*)d_in[8];
    const float* Wk     = (const float*)d_in[9];
    const float* bk     = (const float*)d_in[10];
    const float* Wv     = (const float*)d_in[11];
    const float* bv     = (const float*)d_in[12];
    const float* ln2_g  = (const float*)d_in[13];
    const float* ln2_b  = (const float*)d_in[14];
    const float* W1     = (const float*)d_in[15];
    const float* b1     = (const float*)d_in[16];
    const float* W2     = (const float*)d_in[17];
    const float* b2     = (const float*)d_in[18];
    const float* Wh     = (const float*)d_in[19];
    const float* bh     = (const float*)d_in[20];
    float* out = (float*)d_out;

    float *pA, *pH, *pX, *pQ, *pK, *pV, *pU;
    cudaGetSymbolAddress((void**)&pA, g_A);
    cudaGetSymbolAddress((void**)&pH, g_H);
    cudaGetSymbolAddress((void**)&pX, g_X);
    cudaGetSymbolAddress((void**)&pQ, g_Q);
    cudaGetSymbolAddress((void**)&pK, g_K);
    cudaGetSymbolAddress((void**)&pV, g_V);
    cudaGetSymbolAddress((void**)&pU, g_U);

    cudaFuncSetAttribute(attn_kernel,
                         cudaFuncAttributeMaxDynamicSharedMemorySize,
                         ATTN_SMEM_BYTES);

    // Patch embed: (6272 x 768) @ (768 x 768)
    patchify_kernel<<<(BB*NPAT*DIM + 255)/256, 256>>>(images);
    mma_gemm_kernel<0><<<dim3(DIM/BN, (BB*NPAT+BM-1)/BM), 256>>>(
        pA, DIM, Wp, DIM, bp, pH, DIM, BB*NPAT, DIM);
    assemble_kernel<<<(NTOK*DIM + 255)/256, 256>>>(cls, pos);

    for (int l = 0; l < NL; l++) {
        ln_kernel<<<NTOK, 256>>>(pX, pH, ln1_g + l*DIM, ln1_b + l*DIM);
        qkv_mma_kernel<<<dim3(1, MT128, NHD*3), 256>>>(Wq, bq, Wk, bk, Wv, bv, l);
        attn_kernel<<<BB*NHD, 128, ATTN_SMEM_BYTES>>>(pQ, pK, pV, pX);
        ln_kernel<<<NTOK, 256>>>(pX, pH, ln2_g + l*DIM, ln2_b + l*DIM);
        mma_gemm_kernel<1><<<dim3(MLPD/BN, MT128), 256>>>(
            pH, DIM, W1 + (size_t)l*DIM*MLPD, MLPD, b1 + (size_t)l*MLPD,
            pU, MLPD, NTOK, DIM);
        mma_gemm_kernel<2><<<dim3(DIM/BN, MT128), 256>>>(
            pU, MLPD, W2 + (size_t)l*MLPD*DIM, DIM, b2 + (size_t)l*DIM,
            pX, DIM, NTOK, MLPD);
    }

    head_kernel<<<BB, 256>>>(pX, Wh, bh, out);
}

// round 12
// speedup vs baseline: 1.4890x; 1.4859x over previous
#include <cuda_runtime.h>
#include <math.h>
#include <stdint.h>

#define BB   32
#define SEQ  197
#define DIM  768
#define NHD  12
#define HD   64
#define NL   12
#define NCLS 1000
#define MLPD 3072
#define NTOK (BB*SEQ)     // 6304
#define NPAT 196
#define MT128 ((NTOK+127)/128)   // 50 M-tiles of 128

// -------------------- scratch (device globals; no allocation allowed) -----
__device__ float g_X[NTOK*DIM];
__device__ float g_H[NTOK*DIM];
__device__ float g_A[BB*NPAT*DIM];
__device__ float g_Q[NTOK*DIM];
__device__ float g_K[NTOK*DIM];
__device__ float g_V[NTOK*DIM];
__device__ float g_U[(size_t)NTOK*MLPD];

// -------------------- patchify: (B,C,224,224) -> (B*196, 768) ------------
__global__ void patchify_kernel(const float* __restrict__ img)
{
    int idx = blockIdx.x*256 + threadIdx.x;
    const int total = BB*NPAT*DIM;
    if (idx >= total) return;
    int f = idx % DIM;
    int p = (idx / DIM) % NPAT;
    int b = idx / (DIM*NPAT);
    int c = f >> 8;
    int rem = f & 255;
    int i = rem >> 4;
    int j = rem & 15;
    int pr = p / 14, pc = p % 14;
    g_A[idx] = img[(((size_t)b*3 + c)*224 + (pr*16+i))*224 + (pc*16+j)];
}

// -------------------- assemble tokens: cls + embed + pos -> X ------------
__global__ void assemble_kernel(const float* __restrict__ cls,
                                const float* __restrict__ pos)
{
    int idx = blockIdx.x*256 + threadIdx.x;
    if (idx >= NTOK*DIM) return;
    int d = idx % DIM;
    int s = (idx / DIM) % SEQ;
    int b = idx / (DIM*SEQ);
    float v = (s == 0) ? cls[d] : g_H[((size_t)b*NPAT + (s-1))*DIM + d];
    g_X[idx] = v + pos[s*DIM + d];
}

// ==================== TF32x3 tensor-core GEMM v2 ==========================
// 128x64 C-tile, 256 threads (8 warps 4x2), warp tile 32x32, BK=32.
// hi/lo tf32 split done ONCE at smem store; register-staged global prefetch.
// EPI 0: C = acc + bias ; 1: C = gelu(acc+bias) ; 2: C += acc + bias

#define BM 128
#define BN 64
#define BKK 32
#define ASTR (BKK+4)   // 36
#define BSTR (BN+8)    // 72
#define GEMM_SMEM ((2*BM*ASTR + 2*BKK*BSTR)*4)   // 55296 bytes

__device__ __forceinline__ void split_tf32(float x, float& hi, float& lo)
{
    uint32_t h;
    asm("cvt.rna.tf32.f32 %0, %1;" : "=r"(h) : "f"(x));
    float hf = __uint_as_float(h);
    float r = x - hf;
    uint32_t l;
    asm("cvt.rna.tf32.f32 %0, %1;" : "=r"(l) : "f"(r));
    hi = hf; lo = __uint_as_float(l);
}

__device__ __forceinline__ void mma_tf32(float* cc, const uint32_t* a, const uint32_t* b)
{
    asm volatile(
        "mma.sync.aligned.m16n8k8.row.col.f32.tf32.tf32.f32 "
        "{%0,%1,%2,%3}, {%4,%5,%6,%7}, {%8,%9}, {%0,%1,%2,%3};\n"
        : "+f"(cc[0]), "+f"(cc[1]), "+f"(cc[2]), "+f"(cc[3])
        : "r"(a[0]), "r"(a[1]), "r"(a[2]), "r"(a[3]),
          "r"(b[0]), "r"(b[1]));
}

template<int EPI>
__device__ __forceinline__ void mma_gemm_tile(
    const float* __restrict__ A, int lda,
    const float* __restrict__ Bm, int ldb,
    const float* __restrict__ bias,
    float* __restrict__ C, int ldc,
    int M, int K, int m0, int n0)
{
    extern __shared__ float smb[];
    float (*AsH)[ASTR] = (float(*)[ASTR])(smb);
    float (*AsL)[ASTR] = (float(*)[ASTR])(smb + BM*ASTR);
    float (*BsH)[BSTR] = (float(*)[BSTR])(smb + 2*BM*ASTR);
    float (*BsL)[BSTR] = (float(*)[BSTR])(smb + 2*BM*ASTR + BKK*BSTR);

    int tid  = threadIdx.x;
    int lane = tid & 31, wid = tid >> 5;
    int warpM = wid >> 1, warpN = wid & 1;
    int g = lane >> 2, c = lane & 3;

    int arow = tid >> 3, ac4 = tid & 7;    // A: 4 rows (arow + 32*i), cols ac4*4..+3
    int brow = tid >> 4, bc4 = tid & 15;   // B: 2 rows (brow + 16*i), cols bc4*4..+3

    float acc[2][4][4] = {};
    float4 ra[4], rb[2];

    // ---- prologue: load first tile ----
#pragma unroll
    for (int i = 0; i < 4; i++) {
        int gm = m0 + arow + i*32;
        ra[i] = (gm < M) ? *(const float4*)&A[(size_t)gm*lda + ac4*4]
                         : make_float4(0.f,0.f,0.f,0.f);
    }
#pragma unroll
    for (int i = 0; i < 2; i++)
        rb[i] = *(const float4*)&Bm[(size_t)(brow + i*16)*ldb + n0 + bc4*4];

    for (int k0 = 0; k0 < K; k0 += BKK) {
        // ---- split+store staged tile to smem ----
#pragma unroll
        for (int i = 0; i < 4; i++) {
            int row = arow + i*32;
            float4 hi4, lo4;
            split_tf32(ra[i].x, hi4.x, lo4.x);
            split_tf32(ra[i].y, hi4.y, lo4.y);
            split_tf32(ra[i].z, hi4.z, lo4.z);
            split_tf32(ra[i].w, hi4.w, lo4.w);
            *(float4*)&AsH[row][ac4*4] = hi4;
            *(float4*)&AsL[row][ac4*4] = lo4;
        }
#pragma unroll
        for (int i = 0; i < 2; i++) {
            int row = brow + i*16;
            float4 hi4, lo4;
            split_tf32(rb[i].x, hi4.x, lo4.x);
            split_tf32(rb[i].y, hi4.y, lo4.y);
            split_tf32(rb[i].z, hi4.z, lo4.z);
            split_tf32(rb[i].w, hi4.w, lo4.w);
            *(float4*)&BsH[row][bc4*4] = hi4;
            *(float4*)&BsL[row][bc4*4] = lo4;
        }
        __syncthreads();

        // ---- prefetch next tile into registers ----
        if (k0 + BKK < K) {
            int kn = k0 + BKK;
#pragma unroll
            for (int i = 0; i < 4; i++) {
                int gm = m0 + arow + i*32;
                ra[i] = (gm < M) ? *(const float4*)&A[(size_t)gm*lda + kn + ac4*4]
                                 : make_float4(0.f,0.f,0.f,0.f);
            }
#pragma unroll
            for (int i = 0; i < 2; i++)
                rb[i] = *(const float4*)&Bm[(size_t)(kn + brow + i*16)*ldb + n0 + bc4*4];
        }

        // ---- compute: 4 k8 steps, pure LDS + HMMA ----
#pragma unroll
        for (int kk = 0; kk < BKK; kk += 8) {
            uint32_t ah[2][4], al[2][4];
#pragma unroll
            for (int mt = 0; mt < 2; mt++) {
                int r = warpM*32 + mt*16 + g;
                ah[mt][0] = __float_as_uint(AsH[r  ][kk + c]);
                ah[mt][1] = __float_as_uint(AsH[r+8][kk + c]);
                ah[mt][2] = __float_as_uint(AsH[r  ][kk + c + 4]);
                ah[mt][3] = __float_as_uint(AsH[r+8][kk + c + 4]);
                al[mt][0] = __float_as_uint(AsL[r  ][kk + c]);
                al[mt][1] = __float_as_uint(AsL[r+8][kk + c]);
                al[mt][2] = __float_as_uint(AsL[r  ][kk + c + 4]);
                al[mt][3] = __float_as_uint(AsL[r+8][kk + c + 4]);
            }
            uint32_t bh[4][2], bl[4][2];
#pragma unroll
            for (int nt = 0; nt < 4; nt++) {
                int ncol = warpN*32 + nt*8 + g;
                bh[nt][0] = __float_as_uint(BsH[kk + c    ][ncol]);
                bh[nt][1] = __float_as_uint(BsH[kk + c + 4][ncol]);
                bl[nt][0] = __float_as_uint(BsL[kk + c    ][ncol]);
                bl[nt][1] = __float_as_uint(BsL[kk + c + 4][ncol]);
            }
#pragma unroll
            for (int mt = 0; mt < 2; mt++)
#pragma unroll
                for (int nt = 0; nt < 4; nt++) {
                    mma_tf32(acc[mt][nt], ah[mt], bl[nt]);
                    mma_tf32(acc[mt][nt], al[mt], bh[nt]);
                    mma_tf32(acc[mt][nt], ah[mt], bh[nt]);
                }
        }
        __syncthreads();
    }

    // ---- epilogue ----
#pragma unroll
    for (int mt = 0; mt < 2; mt++) {
#pragma unroll
        for (int nt = 0; nt < 4; nt++) {
            int r0  = m0 + warpM*32 + mt*16 + g;
            int col = n0 + warpN*32 + nt*8 + 2*c;
#pragma unroll
            for (int half = 0; half < 2; half++) {
                int gm = r0 + half*8;
                if (gm >= M) continue;
#pragma unroll
                for (int jj = 0; jj < 2; jj++) {
                    int gn = col + jj;
                    float v = acc[mt][nt][half*2 + jj] + bias[gn];
                    float* cp = &C[(size_t)gm*ldc + gn];
                    if (EPI == 1) v = 0.5f*v*(1.f + erff(v*0.70710678118654752f));
                    if (EPI == 2) v += *cp;
                    *cp = v;
                }
            }
        }
    }
}

template<int EPI>
__global__ __launch_bounds__(256) void mma_gemm_kernel(
    const float* __restrict__ A, int lda,
    const float* __restrict__ Bm, int ldb,
    const float* __restrict__ bias,
    float* __restrict__ C, int ldc, int M, int K)
{
    mma_gemm_tile<EPI>(A, lda, Bm, ldb, bias, C, ldc, M, K,
                       blockIdx.y*BM, blockIdx.x*BN);
}

// per-head QKV via the same MMA tile. grid: (1, Mtiles128, 36 = 12 heads x 3)
__global__ __launch_bounds__(256) void qkv_mma_kernel(
    const float* __restrict__ Wq, const float* __restrict__ bq,
    const float* __restrict__ Wk, const float* __restrict__ bk,
    const float* __restrict__ Wv, const float* __restrict__ bv,
    int layer)
{
    int z = blockIdx.z;
    int h = z % NHD, t = z / NHD;
    const float* W; const float* bi; float* C;
    if (t == 0)      { W = Wq; bi = bq; C = g_Q; }
    else if (t == 1) { W = Wk; bi = bk; C = g_K; }
    else             { W = Wv; bi = bv; C = g_V; }
    size_t off = (size_t)layer*NHD + h;
    mma_gemm_tile<0>(g_H + h*HD, DIM,
                     W + off*HD*HD, HD,
                     bi + off*HD,
                     C + h*HD, DIM,
                     NTOK, HD, blockIdx.y*BM, 0);
}

// -------------------- layernorm ------------------------------------------
__global__ __launch_bounds__(256) void ln_kernel(
    const float* __restrict__ X, float* __restrict__ H,
    const float* __restrict__ gw, const float* __restrict__ bw)
{
    __shared__ float rs[8], rq[8];
    int row = blockIdx.x, tid = threadIdx.x;
    int lane = tid & 31, wid = tid >> 5;
    const float* x = X + (size_t)row*DIM;
    float v0 = x[tid], v1 = x[tid+256], v2 = x[tid+512];
    float s = v0+v1+v2;
    float q = v0*v0 + v1*v1 + v2*v2;
#pragma unroll
    for (int o = 16; o; o >>= 1) {
        s += __shfl_xor_sync(0xffffffffu, s, o);
        q += __shfl_xor_sync(0xffffffffu, q, o);
    }
    if (lane == 0) { rs[wid] = s; rq[wid] = q; }
    __syncthreads();
    if (tid == 0) {
        float ts = 0.f, tq = 0.f;
        for (int w = 0; w < 8; w++) { ts += rs[w]; tq += rq[w]; }
        rs[0] = ts; rq[0] = tq;
    }
    __syncthreads();
    float mean = rs[0]*(1.0f/DIM);
    float var  = rq[0]*(1.0f/DIM) - mean*mean;
    float inv  = rsqrtf(var + 1e-5f);
    float* hrow = H + (size_t)row*DIM;
    hrow[tid]     = (v0-mean)*inv*gw[tid]     + bw[tid];
    hrow[tid+256] = (v1-mean)*inv*gw[tid+256] + bw[tid+256];
    hrow[tid+512] = (v2-mean)*inv*gw[tid+512] + bw[tid+512];
}

// -------------------- attention v2: warp-parallel queries ----------------
// One block per (b,h), 4 warps, each warp owns queries s = wid, wid+4, ...
// No block barriers inside the query loop; per-warp q/p smem buffers.
#define PSTR 208
#define ATTN_SMEM_FLOATS (2*SEQ*HD + 4*HD + 4*PSTR)
#define ATTN_SMEM_BYTES  (ATTN_SMEM_FLOATS*4)

__global__ __launch_bounds__(128) void attn_kernel(
    const float* __restrict__ Q, const float* __restrict__ K,
    const float* __restrict__ V, float* __restrict__ X)
{
    extern __shared__ float sm[];
    float* Ks = sm;               // SEQ*HD
    float* Vs = Ks + SEQ*HD;      // SEQ*HD
    float* qs = Vs + SEQ*HD;      // 4*HD
    float* ps = qs + 4*HD;        // 4*PSTR

    int bh = blockIdx.x;
    int b = bh / NHD, h = bh % NHD;
    int tid = threadIdx.x;
    int lane = tid & 31, wid = tid >> 5;
    size_t base = (size_t)b*SEQ*DIM + (size_t)h*HD;

    // cooperative load of K,V tiles (float2, coalesced)
    for (int idx = tid; idx < SEQ*32; idx += 128) {
        int t = idx >> 5, e2 = idx & 31;
        ((float2*)Ks)[idx] = *(const float2*)&K[base + (size_t)t*DIM + 2*e2];
        ((float2*)Vs)[idx] = *(const float2*)&V[base + (size_t)t*DIM + 2*e2];
    }
    __syncthreads();

    float* myq = qs + wid*HD;
    float* myp = ps + wid*PSTR;
    const float2* q2 = (const float2*)myq;
    const float2* vr = (const float2*)Vs;

    for (int s = wid; s < SEQ; s += 4) {
        // load q into per-warp smem
        *(float2*)&myq[2*lane] = *(const float2*)&Q[base + (size_t)s*DIM + 2*lane];
        __syncwarp();

        // scores (rotated float2 reads: conflict-free)
        float lm = -1e30f;
        for (int j = lane; j < SEQ; j += 32) {
            const float2* kr = (const float2*)&Ks[j*HD];
            float d = 0.f;
#pragma unroll
            for (int e2 = 0; e2 < 32; e2++) {
                int ee = (e2 + lane) & 31;
                float2 kv = kr[ee];
                float2 qv = q2[ee];
                d = fmaf(qv.x, kv.x, d);
                d = fmaf(qv.y, kv.y, d);
            }
            d *= 0.125f;                 // 1/sqrt(64)
            myp[j] = d;
            lm = fmaxf(lm, d);
        }
#pragma unroll
        for (int o = 16; o; o >>= 1)
            lm = fmaxf(lm, __shfl_xor_sync(0xffffffffu, lm, o));

        // softmax numerator + sum
        float ls = 0.f;
        for (int j = lane; j < SEQ; j += 32) {
            float e = expf(myp[j] - lm);
            myp[j] = e;
            ls += e;
        }
#pragma unroll
        for (int o = 16; o; o >>= 1)
            ls += __shfl_xor_sync(0xffffffffu, ls, o);
        float inv = 1.f / ls;
        __syncwarp();   // myp writes visible to all lanes

        // AV: each lane owns output elems 2*lane, 2*lane+1
        float2 acc = make_float2(0.f, 0.f);
        int t = 0;
        for (; t + 4 <= SEQ; t += 4) {
#pragma unroll
            for (int u = 0; u < 4; u++) {
                float p = myp[t+u];
                float2 vv = vr[(t+u)*32 + lane];
                acc.x = fmaf(p, vv.x, acc.x);
                acc.y = fmaf(p, vv.y, acc.y);
            }
        }
        for (; t < SEQ; t++) {
            float p = myp[t];
            float2 vv = vr[t*32 + lane];
            acc.x = fmaf(p, vv.x, acc.x);
            acc.y = fmaf(p, vv.y, acc.y);
        }

        float* xp = &X[base + (size_t)s*DIM + 2*lane];
        float2 xo = *(float2*)xp;
        xo.x += acc.x * inv;
        xo.y += acc.y * inv;
        *(float2*)xp = xo;
        __syncwarp();   // protect myq/myp for next iteration
    }
}

// -------------------- classifier head + softmax --------------------------
__global__ __launch_bounds__(256) void head_kernel(
    const float* __restrict__ X, const float* __restrict__ Wh,
    const float* __restrict__ bh, float* __restrict__ out)
{
    __shared__ float xr[DIM];
    __shared__ float lg[NCLS];
    __shared__ float red[8];
    int b = blockIdx.x, tid = threadIdx.x;
    int lane = tid & 31, wid = tid >> 5;

    for (int d = tid; d < DIM; d += 256) xr[d] = X[(size_t)b*SEQ*DIM + d];
    __syncthreads();

    for (int n = tid; n < NCLS; n += 256) {
        float a = bh[n];
        for (int k = 0; k < DIM; k++)
            a = fmaf(xr[k], Wh[(size_t)k*NCLS + n], a);
        lg[n] = a;
    }
    __syncthreads();

    float lm = -1e30f;
    for (int n = tid; n < NCLS; n += 256) lm = fmaxf(lm, lg[n]);
#pragma unroll
    for (int o = 16; o; o >>= 1) lm = fmaxf(lm, __shfl_xor_sync(0xffffffffu, lm, o));
    if (lane == 0) red[wid] = lm;
    __syncthreads();
    if (tid == 0) {
        float m = red[0];
        for (int w = 1; w < 8; w++) m = fmaxf(m, red[w]);
        red[0] = m;
    }
    __syncthreads();
    float mx = red[0];

    float ls = 0.f;
    for (int n = tid; n < NCLS; n += 256) {
        float e = expf(lg[n] - mx);
        lg[n] = e;
        ls += e;
    }
#pragma unroll
    for (int o = 16; o; o >>= 1) ls += __shfl_xor_sync(0xffffffffu, ls, o);
    __syncthreads();
    if (lane == 0) red[wid] = ls;
    __syncthreads();
    if (tid == 0) {
        float s2 = 0.f;
        for (int w = 0; w < 8; w++) s2 += red[w];
        red[0] = s2;
    }
    __syncthreads();
    float inv = 1.f / red[0];
    for (int n = tid; n < NCLS; n += 256)
        out[(size_t)b*NCLS + n] = lg[n]*inv;
}

// -------------------- launch ---------------------------------------------
extern "C" void kernel_launch(void* const* d_in, const int* in_sizes, int n_in,
                              void* d_out, int out_size)
{
    (void)in_sizes; (void)n_in; (void)out_size;
    const float* images = (const float*)d_in[0];
    const float* Wp     = (const float*)d_in[1];
    const float* bp     = (const float*)d_in[2];
    const float* cls    = (const float*)d_in[3];
    const float* pos    = (const float*)d_in[4];
    const float* ln1_g  = (const float*)d_in[5];
    const float* ln1_b  = (const float*)d_in[6];
    const float* Wq     = (const float*)d_in[7];
    const float* bq     = (const float*)d_in[8];
    const float* Wk     = (const float*)d_in[9];
    const float* bk     = (const float*)d_in[10];
    const float* Wv     = (const float*)d_in[11];
    const float* bv     = (const float*)d_in[12];
    const float* ln2_g  = (const float*)d_in[13];
    const float* ln2_b  = (const float*)d_in[14];
    const float* W1     = (const float*)d_in[15];
    const float* b1     = (const float*)d_in[16];
    const float* W2     = (const float*)d_in[17];
    const float* b2     = (const float*)d_in[18];
    const float* Wh     = (const float*)d_in[19];
    const float* bh     = (const float*)d_in[20];
    float* out = (float*)d_out;

    float *pA, *pH, *pX, *pQ, *pK, *pV, *pU;
    cudaGetSymbolAddress((void**)&pA, g_A);
    cudaGetSymbolAddress((void**)&pH, g_H);
    cudaGetSymbolAddress((void**)&pX, g_X);
    cudaGetSymbolAddress((void**)&pQ, g_Q);
    cudaGetSymbolAddress((void**)&pK, g_K);
    cudaGetSymbolAddress((void**)&pV, g_V);
    cudaGetSymbolAddress((void**)&pU, g_U);

    cudaFuncSetAttribute(mma_gemm_kernel<0>,
        cudaFuncAttributeMaxDynamicSharedMemorySize, GEMM_SMEM);
    cudaFuncSetAttribute(mma_gemm_kernel<1>,
        cudaFuncAttributeMaxDynamicSharedMemorySize, GEMM_SMEM);
    cudaFuncSetAttribute(mma_gemm_kernel<2>,
        cudaFuncAttributeMaxDynamicSharedMemorySize, GEMM_SMEM);
    cudaFuncSetAttribute(qkv_mma_kernel,
        cudaFuncAttributeMaxDynamicSharedMemorySize, GEMM_SMEM);
    cudaFuncSetAttribute(attn_kernel,
        cudaFuncAttributeMaxDynamicSharedMemorySize, ATTN_SMEM_BYTES);

    // Patch embed: (6272 x 768) @ (768 x 768)
    patchify_kernel<<<(BB*NPAT*DIM + 255)/256, 256>>>(images);
    mma_gemm_kernel<0><<<dim3(DIM/BN, (BB*NPAT+BM-1)/BM), 256, GEMM_SMEM>>>(
        pA, DIM, Wp, DIM, bp, pH, DIM, BB*NPAT, DIM);
    assemble_kernel<<<(NTOK*DIM + 255)/256, 256>>>(cls, pos);

    for (int l = 0; l < NL; l++) {
        ln_kernel<<<NTOK, 256>>>(pX, pH, ln1_g + l*DIM, ln1_b + l*DIM);
        qkv_mma_kernel<<<dim3(1, MT128, NHD*3), 256, GEMM_SMEM>>>(
            Wq, bq, Wk, bk, Wv, bv, l);
        attn_kernel<<<BB*NHD, 128, ATTN_SMEM_BYTES>>>(pQ, pK, pV, pX);
        ln_kernel<<<NTOK, 256>>>(pX, pH, ln2_g + l*DIM, ln2_b + l*DIM);
        mma_gemm_kernel<1><<<dim3(MLPD/BN, MT128), 256, GEMM_SMEM>>>(
            pH, DIM, W1 + (size_t)l*DIM*MLPD, MLPD, b1 + (size_t)l*MLPD,
            pU, MLPD, NTOK, DIM);
        mma_gemm_kernel<2><<<dim3(DIM/BN, MT128), 256, GEMM_SMEM>>>(
            pU, MLPD, W2 + (size_t)l*MLPD*DIM, DIM, b2 + (size_t)l*DIM,
            pX, DIM, NTOK, MLPD);
    }

    head_kernel<<<BB, 256>>>(pX, Wh, bh, out);
}

// round 13
// speedup vs baseline: 2.0677x; 1.3886x over previous
#include <cuda_runtime.h>
#include <cuda_fp16.h>
#include <math.h>
#include <stdint.h>

#define BB   32
#define SEQ  197
#define DIM  768
#define NHD  12
#define HD   64
#define NL   12
#define NCLS 1000
#define MLPD 3072
#define NTOK (BB*SEQ)     // 6304
#define NPAT 196
#define MT128 ((NTOK+127)/128)   // 50 M-tiles of 128

// -------------------- scratch (device globals; no allocation allowed) -----
__device__ float g_X[NTOK*DIM];
__device__ float g_H[NTOK*DIM];
__device__ float g_A[BB*NPAT*DIM];
__device__ float g_Q[NTOK*DIM];
__device__ float g_K[NTOK*DIM];
__device__ float g_V[NTOK*DIM];
__device__ float g_U[(size_t)NTOK*MLPD];

// -------------------- patchify: (B,C,224,224) -> (B*196, 768) ------------
__global__ void patchify_kernel(const float* __restrict__ img)
{
    int idx = blockIdx.x*256 + threadIdx.x;
    const int total = BB*NPAT*DIM;
    if (idx >= total) return;
    int f = idx % DIM;
    int p = (idx / DIM) % NPAT;
    int b = idx / (DIM*NPAT);
    int c = f >> 8;
    int rem = f & 255;
    int i = rem >> 4;
    int j = rem & 15;
    int pr = p / 14, pc = p % 14;
    g_A[idx] = img[(((size_t)b*3 + c)*224 + (pr*16+i))*224 + (pc*16+j)];
}

// -------------------- assemble tokens: cls + embed + pos -> X ------------
__global__ void assemble_kernel(const float* __restrict__ cls,
                                const float* __restrict__ pos)
{
    int idx = blockIdx.x*256 + threadIdx.x;
    if (idx >= NTOK*DIM) return;
    int d = idx % DIM;
    int s = (idx / DIM) % SEQ;
    int b = idx / (DIM*SEQ);
    float v = (s == 0) ? cls[d] : g_H[((size_t)b*NPAT + (s-1))*DIM + d];
    g_X[idx] = v + pos[s*DIM + d];
}

// ==================== FP16x3 tensor-core GEMM (m16n8k16) ==================
// 128x64 C-tile, 256 threads (8 warps 4x2), warp tile 32x32, BK=32.
// f32 operand split into fp16 hi + fp16 lo ONCE at smem-store time.
// Double-buffered smem: one __syncthreads per K-iteration.
// Smem holds packed half2 words:
//   A: [128][16 kpairs] stride 20 words;  B: [16 kpairs][64 n] stride 72 words.
// EPI 0: C = acc + bias ; 1: C = gelu(acc+bias) ; 2: C += acc + bias

#define BM 128
#define BN 64
#define BKK 32
#define AWS 20                 // A row stride in words
#define BWS 72                 // B kpair-row stride in words
#define A_STG (BM*AWS)         // 2560 words per stage (per hi or lo)
#define B_STG (16*BWS)         // 1152 words per stage
#define OFF_AH 0
#define OFF_AL (2*A_STG)       // 5120
#define OFF_BH (4*A_STG)       // 10240
#define OFF_BL (4*A_STG + 2*B_STG)  // 12544
#define GEMM_WORDS (4*A_STG + 4*B_STG)   // 14848
#define GEMM_SMEM (GEMM_WORDS*4)         // 59392 bytes

__device__ __forceinline__ void mma_f16(float* cc, const uint32_t* a, const uint32_t* b)
{
    asm volatile(
        "mma.sync.aligned.m16n8k16.row.col.f32.f16.f16.f32 "
        "{%0,%1,%2,%3}, {%4,%5,%6,%7}, {%8,%9}, {%0,%1,%2,%3};\n"
        : "+f"(cc[0]), "+f"(cc[1]), "+f"(cc[2]), "+f"(cc[3])
        : "r"(a[0]), "r"(a[1]), "r"(a[2]), "r"(a[3]),
          "r"(b[0]), "r"(b[1]));
}

// pack two floats -> half2 hi word + half2 lo (residual) word
__device__ __forceinline__ void split2(float x, float y, uint32_t& hw, uint32_t& lw)
{
    __half2 h = __floats2half2_rn(x, y);
    float2 hf = __half22float2(h);
    __half2 l = __floats2half2_rn(x - hf.x, y - hf.y);
    hw = *(uint32_t*)&h;
    lw = *(uint32_t*)&l;
}

template<int EPI>
__device__ __forceinline__ void mma_gemm_tile(
    const float* __restrict__ A, int lda,
    const float* __restrict__ Bm, int ldb,
    const float* __restrict__ bias,
    float* __restrict__ C, int ldc,
    int M, int K, int m0, int n0)
{
    extern __shared__ uint32_t smw[];

    int tid  = threadIdx.x;
    int lane = tid & 31, wid = tid >> 5;
    int warpM = wid >> 1, warpN = wid & 1;
    int g = lane >> 2, c = lane & 3;

    int arow = tid >> 3, ac4 = tid & 7;    // A: rows arow+32i, k-cols ac4*4..+3
    int bp   = tid >> 4, bc4 = tid & 15;   // B: kpair bp (k=2bp,2bp+1), n-cols bc4*4..+3

    float acc[2][4][4] = {};
    float4 ra[4], rb0, rb1;

    // ---- prologue: LDG tile 0 ----
#pragma unroll
    for (int i = 0; i < 4; i++) {
        int gm = m0 + arow + i*32;
        ra[i] = (gm < M) ? *(const float4*)&A[(size_t)gm*lda + ac4*4]
                         : make_float4(0.f,0.f,0.f,0.f);
    }
    rb0 = *(const float4*)&Bm[(size_t)(2*bp  )*ldb + n0 + bc4*4];
    rb1 = *(const float4*)&Bm[(size_t)(2*bp+1)*ldb + n0 + bc4*4];

    int p = 0;
    for (int k0 = 0; k0 < K; k0 += BKK) {
        // ---- split + store staged tile into buffer p ----
        uint32_t* AH = smw + OFF_AH + p*A_STG;
        uint32_t* AL = smw + OFF_AL + p*A_STG;
        uint32_t* BH = smw + OFF_BH + p*B_STG;
        uint32_t* BL = smw + OFF_BL + p*B_STG;
#pragma unroll
        for (int i = 0; i < 4; i++) {
            int row = arow + i*32;
            uint32_t h0,h1,l0,l1;
            split2(ra[i].x, ra[i].y, h0, l0);
            split2(ra[i].z, ra[i].w, h1, l1);
            *(uint2*)&AH[row*AWS + ac4*2] = make_uint2(h0, h1);
            *(uint2*)&AL[row*AWS + ac4*2] = make_uint2(l0, l1);
        }
        {
            float r0[4] = {rb0.x, rb0.y, rb0.z, rb0.w};
            float r1[4] = {rb1.x, rb1.y, rb1.z, rb1.w};
            uint32_t hw[4], lw[4];
#pragma unroll
            for (int j = 0; j < 4; j++)
                split2(r0[j], r1[j], hw[j], lw[j]);   // word = {k even, k odd}
            *(uint4*)&BH[bp*BWS + bc4*4] = make_uint4(hw[0],hw[1],hw[2],hw[3]);
            *(uint4*)&BL[bp*BWS + bc4*4] = make_uint4(lw[0],lw[1],lw[2],lw[3]);
        }
        __syncthreads();

        // ---- prefetch next tile into registers ----
        if (k0 + BKK < K) {
            int kn = k0 + BKK;
#pragma unroll
            for (int i = 0; i < 4; i++) {
                int gm = m0 + arow + i*32;
                ra[i] = (gm < M) ? *(const float4*)&A[(size_t)gm*lda + kn + ac4*4]
                                 : make_float4(0.f,0.f,0.f,0.f);
            }
            rb0 = *(const float4*)&Bm[(size_t)(kn + 2*bp  )*ldb + n0 + bc4*4];
            rb1 = *(const float4*)&Bm[(size_t)(kn + 2*bp+1)*ldb + n0 + bc4*4];
        }

        // ---- compute from buffer p: 2 k16 steps ----
#pragma unroll
        for (int kk = 0; kk < 2; kk++) {
            int ko = kk*8;
            uint32_t ah[2][4], al[2][4];
#pragma unroll
            for (int mt = 0; mt < 2; mt++) {
                int r = warpM*32 + mt*16 + g;
                ah[mt][0] = AH[ r   *AWS + ko + c];
                ah[mt][1] = AH[(r+8)*AWS + ko + c];
                ah[mt][2] = AH[ r   *AWS + ko + c + 4];
                ah[mt][3] = AH[(r+8)*AWS + ko + c + 4];
                al[mt][0] = AL[ r   *AWS + ko + c];
                al[mt][1] = AL[(r+8)*AWS + ko + c];
                al[mt][2] = AL[ r   *AWS + ko + c + 4];
                al[mt][3] = AL[(r+8)*AWS + ko + c + 4];
            }
            uint32_t bh[4][2], bl[4][2];
#pragma unroll
            for (int nt = 0; nt < 4; nt++) {
                int ncol = warpN*32 + nt*8 + g;
                bh[nt][0] = BH[(ko + c    )*BWS + ncol];
                bh[nt][1] = BH[(ko + c + 4)*BWS + ncol];
                bl[nt][0] = BL[(ko + c    )*BWS + ncol];
                bl[nt][1] = BL[(ko + c + 4)*BWS + ncol];
            }
#pragma unroll
            for (int mt = 0; mt < 2; mt++)
#pragma unroll
                for (int nt = 0; nt < 4; nt++) {
                    mma_f16(acc[mt][nt], ah[mt], bl[nt]);
                    mma_f16(acc[mt][nt], al[mt], bh[nt]);
                    mma_f16(acc[mt][nt], ah[mt], bh[nt]);
                }
        }
        p ^= 1;   // next store goes to other buffer; one barrier per iter
    }

    // ---- epilogue ----
#pragma unroll
    for (int mt = 0; mt < 2; mt++) {
#pragma unroll
        for (int nt = 0; nt < 4; nt++) {
            int r0  = m0 + warpM*32 + mt*16 + g;
            int col = n0 + warpN*32 + nt*8 + 2*c;
#pragma unroll
            for (int half = 0; half < 2; half++) {
                int gm = r0 + half*8;
                if (gm >= M) continue;
#pragma unroll
                for (int jj = 0; jj < 2; jj++) {
                    int gn = col + jj;
                    float v = acc[mt][nt][half*2 + jj] + bias[gn];
                    float* cp = &C[(size_t)gm*ldc + gn];
                    if (EPI == 1) v = 0.5f*v*(1.f + erff(v*0.70710678118654752f));
                    if (EPI == 2) v += *cp;
                    *cp = v;
                }
            }
        }
    }
}

template<int EPI>
__global__ __launch_bounds__(256) void mma_gemm_kernel(
    const float* __restrict__ A, int lda,
    const float* __restrict__ Bm, int ldb,
    const float* __restrict__ bias,
    float* __restrict__ C, int ldc, int M, int K)
{
    mma_gemm_tile<EPI>(A, lda, Bm, ldb, bias, C, ldc, M, K,
                       blockIdx.y*BM, blockIdx.x*BN);
}

// per-head QKV via the same MMA tile. grid: (1, Mtiles128, 36 = 12 heads x 3)
__global__ __launch_bounds__(256) void qkv_mma_kernel(
    const float* __restrict__ Wq, const float* __restrict__ bq,
    const float* __restrict__ Wk, const float* __restrict__ bk,
    const float* __restrict__ Wv, const float* __restrict__ bv,
    int layer)
{
    int z = blockIdx.z;
    int h = z % NHD, t = z / NHD;
    const float* W; const float* bi; float* C;
    if (t == 0)      { W = Wq; bi = bq; C = g_Q; }
    else if (t == 1) { W = Wk; bi = bk; C = g_K; }
    else             { W = Wv; bi = bv; C = g_V; }
    size_t off = (size_t)layer*NHD + h;
    mma_gemm_tile<0>(g_H + h*HD, DIM,
                     W + off*HD*HD, HD,
                     bi + off*HD,
                     C + h*HD, DIM,
                     NTOK, HD, blockIdx.y*BM, 0);
}

// -------------------- layernorm ------------------------------------------
__global__ __launch_bounds__(256) void ln_kernel(
    const float* __restrict__ X, float* __restrict__ H,
    const float* __restrict__ gw, const float* __restrict__ bw)
{
    __shared__ float rs[8], rq[8];
    int row = blockIdx.x, tid = threadIdx.x;
    int lane = tid & 31, wid = tid >> 5;
    const float* x = X + (size_t)row*DIM;
    float v0 = x[tid], v1 = x[tid+256], v2 = x[tid+512];
    float s = v0+v1+v2;
    float q = v0*v0 + v1*v1 + v2*v2;
#pragma unroll
    for (int o = 16; o; o >>= 1) {
        s += __shfl_xor_sync(0xffffffffu, s, o);
        q += __shfl_xor_sync(0xffffffffu, q, o);
    }
    if (lane == 0) { rs[wid] = s; rq[wid] = q; }
    __syncthreads();
    if (tid == 0) {
        float ts = 0.f, tq = 0.f;
        for (int w = 0; w < 8; w++) { ts += rs[w]; tq += rq[w]; }
        rs[0] = ts; rq[0] = tq;
    }
    __syncthreads();
    float mean = rs[0]*(1.0f/DIM);
    float var  = rq[0]*(1.0f/DIM) - mean*mean;
    float inv  = rsqrtf(var + 1e-5f);
    float* hrow = H + (size_t)row*DIM;
    hrow[tid]     = (v0-mean)*inv*gw[tid]     + bw[tid];
    hrow[tid+256] = (v1-mean)*inv*gw[tid+256] + bw[tid+256];
    hrow[tid+512] = (v2-mean)*inv*gw[tid+512] + bw[tid+512];
}

// -------------------- attention: warp-parallel queries -------------------
#define PSTR 208
#define ATTN_SMEM_FLOATS (2*SEQ*HD + 4*HD + 4*PSTR)
#define ATTN_SMEM_BYTES  (ATTN_SMEM_FLOATS*4)

__global__ __launch_bounds__(128) void attn_kernel(
    const float* __restrict__ Q, const float* __restrict__ K,
    const float* __restrict__ V, float* __restrict__ X)
{
    extern __shared__ float sm[];
    float* Ks = sm;               // SEQ*HD
    float* Vs = Ks + SEQ*HD;      // SEQ*HD
    float* qs = Vs + SEQ*HD;      // 4*HD
    float* ps = qs + 4*HD;        // 4*PSTR

    int bh = blockIdx.x;
    int b = bh / NHD, h = bh % NHD;
    int tid = threadIdx.x;
    int lane = tid & 31, wid = tid >> 5;
    size_t base = (size_t)b*SEQ*DIM + (size_t)h*HD;

    for (int idx = tid; idx < SEQ*32; idx += 128) {
        int t = idx >> 5, e2 = idx & 31;
        ((float2*)Ks)[idx] = *(const float2*)&K[base + (size_t)t*DIM + 2*e2];
        ((float2*)Vs)[idx] = *(const float2*)&V[base + (size_t)t*DIM + 2*e2];
    }
    __syncthreads();

    float* myq = qs + wid*HD;
    float* myp = ps + wid*PSTR;
    const float2* q2 = (const float2*)myq;
    const float2* vr = (const float2*)Vs;

    for (int s = wid; s < SEQ; s += 4) {
        *(float2*)&myq[2*lane] = *(const float2*)&Q[base + (size_t)s*DIM + 2*lane];
        __syncwarp();

        float lm = -1e30f;
        for (int j = lane; j < SEQ; j += 32) {
            const float2* kr = (const float2*)&Ks[j*HD];
            float d = 0.f;
#pragma unroll
            for (int e2 = 0; e2 < 32; e2++) {
                int ee = (e2 + lane) & 31;
                float2 kv = kr[ee];
                float2 qv = q2[ee];
                d = fmaf(qv.x, kv.x, d);
                d = fmaf(qv.y, kv.y, d);
            }
            d *= 0.125f;
            myp[j] = d;
            lm = fmaxf(lm, d);
        }
#pragma unroll
        for (int o = 16; o; o >>= 1)
            lm = fmaxf(lm, __shfl_xor_sync(0xffffffffu, lm, o));

        float ls = 0.f;
        for (int j = lane; j < SEQ; j += 32) {
            float e = expf(myp[j] - lm);
            myp[j] = e;
            ls += e;
        }
#pragma unroll
        for (int o = 16; o; o >>= 1)
            ls += __shfl_xor_sync(0xffffffffu, ls, o);
        float inv = 1.f / ls;
        __syncwarp();

        float2 acc = make_float2(0.f, 0.f);
        int t = 0;
        for (; t + 4 <= SEQ; t += 4) {
#pragma unroll
            for (int u = 0; u < 4; u++) {
                float p = myp[t+u];
                float2 vv = vr[(t+u)*32 + lane];
                acc.x = fmaf(p, vv.x, acc.x);
                acc.y = fmaf(p, vv.y, acc.y);
            }
        }
        for (; t < SEQ; t++) {
            float p = myp[t];
            float2 vv = vr[t*32 + lane];
            acc.x = fmaf(p, vv.x, acc.x);
            acc.y = fmaf(p, vv.y, acc.y);
        }

        float* xp = &X[base + (size_t)s*DIM + 2*lane];
        float2 xo = *(float2*)xp;
        xo.x += acc.x * inv;
        xo.y += acc.y * inv;
        *(float2*)xp = xo;
        __syncwarp();
    }
}

// -------------------- classifier head + softmax --------------------------
__global__ __launch_bounds__(256) void head_kernel(
    const float* __restrict__ X, const float* __restrict__ Wh,
    const float* __restrict__ bh, float* __restrict__ out)
{
    __shared__ float xr[DIM];
    __shared__ float lg[NCLS];
    __shared__ float red[8];
    int b = blockIdx.x, tid = threadIdx.x;
    int lane = tid & 31, wid = tid >> 5;

    for (int d = tid; d < DIM; d += 256) xr[d] = X[(size_t)b*SEQ*DIM + d];
    __syncthreads();

    for (int n = tid; n < NCLS; n += 256) {
        float a = bh[n];
        for (int k = 0; k < DIM; k++)
            a = fmaf(xr[k], Wh[(size_t)k*NCLS + n], a);
        lg[n] = a;
    }
    __syncthreads();

    float lm = -1e30f;
    for (int n = tid; n < NCLS; n += 256) lm = fmaxf(lm, lg[n]);
#pragma unroll
    for (int o = 16; o; o >>= 1) lm = fmaxf(lm, __shfl_xor_sync(0xffffffffu, lm, o));
    if (lane == 0) red[wid] = lm;
    __syncthreads();
    if (tid == 0) {
        float m = red[0];
        for (int w = 1; w < 8; w++) m = fmaxf(m, red[w]);
        red[0] = m;
    }
    __syncthreads();
    float mx = red[0];

    float ls = 0.f;
    for (int n = tid; n < NCLS; n += 256) {
        float e = expf(lg[n] - mx);
        lg[n] = e;
        ls += e;
    }
#pragma unroll
    for (int o = 16; o; o >>= 1) ls += __shfl_xor_sync(0xffffffffu, ls, o);
    __syncthreads();
    if (lane == 0) red[wid] = ls;
    __syncthreads();
    if (tid == 0) {
        float s2 = 0.f;
        for (int w = 0; w < 8; w++) s2 += red[w];
        red[0] = s2;
    }
    __syncthreads();
    float inv = 1.f / red[0];
    for (int n = tid; n < NCLS; n += 256)
        out[(size_t)b*NCLS + n] = lg[n]*inv;
}

// -------------------- launch ---------------------------------------------
extern "C" void kernel_launch(void* const* d_in, const int* in_sizes, int n_in,
                              void* d_out, int out_size)
{
    (void)in_sizes; (void)n_in; (void)out_size;
    const float* images = (const float*)d_in[0];
    const float* Wp     = (const float*)d_in[1];
    const float* bp     = (const float*)d_in[2];
    const float* cls    = (const float*)d_in[3];
    const float* pos    = (const float*)d_in[4];
    const float* ln1_g  = (const float*)d_in[5];
    const float* ln1_b  = (const float*)d_in[6];
    const float* Wq     = (const float*)d_in[7];
    const float* bq     = (const float*)d_in[8];
    const float* Wk     = (const float*)d_in[9];
    const float* bk     = (const float*)d_in[10];
    const float* Wv     = (const float*)d_in[11];
    const float* bv     = (const float*)d_in[12];
    const float* ln2_g  = (const float*)d_in[13];
    const float* ln2_b  = (const float*)d_in[14];
    const float* W1     = (const float*)d_in[15];
    const float* b1     = (const float*)d_in[16];
    const float* W2     = (const float*)d_in[17];
    const float* b2     = (const float*)d_in[18];
    const float* Wh     = (const float*)d_in[19];
    const float* bh     = (const float*)d_in[20];
    float* out = (float*)d_out;

    float *pA, *pH, *pX, *pQ, *pK, *pV, *pU;
    cudaGetSymbolAddress((void**)&pA, g_A);
    cudaGetSymbolAddress((void**)&pH, g_H);
    cudaGetSymbolAddress((void**)&pX, g_X);
    cudaGetSymbolAddress((void**)&pQ, g_Q);
    cudaGetSymbolAddress((void**)&pK, g_K);
    cudaGetSymbolAddress((void**)&pV, g_V);
    cudaGetSymbolAddress((void**)&pU, g_U);

    cudaFuncSetAttribute(mma_gemm_kernel<0>,
        cudaFuncAttributeMaxDynamicSharedMemorySize, GEMM_SMEM);
    cudaFuncSetAttribute(mma_gemm_kernel<1>,
        cudaFuncAttributeMaxDynamicSharedMemorySize, GEMM_SMEM);
    cudaFuncSetAttribute(mma_gemm_kernel<2>,
        cudaFuncAttributeMaxDynamicSharedMemorySize, GEMM_SMEM);
    cudaFuncSetAttribute(qkv_mma_kernel,
        cudaFuncAttributeMaxDynamicSharedMemorySize, GEMM_SMEM);
    cudaFuncSetAttribute(attn_kernel,
        cudaFuncAttributeMaxDynamicSharedMemorySize, ATTN_SMEM_BYTES);

    // Patch embed: (6272 x 768) @ (768 x 768)
    patchify_kernel<<<(BB*NPAT*DIM + 255)/256, 256>>>(images);
    mma_gemm_kernel<0><<<dim3(DIM/BN, (BB*NPAT+BM-1)/BM), 256, GEMM_SMEM>>>(
        pA, DIM, Wp, DIM, bp, pH, DIM, BB*NPAT, DIM);
    assemble_kernel<<<(NTOK*DIM + 255)/256, 256>>>(cls, pos);

    for (int l = 0; l < NL; l++) {
        ln_kernel<<<NTOK, 256>>>(pX, pH, ln1_g + l*DIM, ln1_b + l*DIM);
        qkv_mma_kernel<<<dim3(1, MT128, NHD*3), 256, GEMM_SMEM>>>(
            Wq, bq, Wk, bk, Wv, bv, l);
        attn_kernel<<<BB*NHD, 128, ATTN_SMEM_BYTES>>>(pQ, pK, pV, pX);
        ln_kernel<<<NTOK, 256>>>(pX, pH, ln2_g + l*DIM, ln2_b + l*DIM);
        mma_gemm_kernel<1><<<dim3(MLPD/BN, MT128), 256, GEMM_SMEM>>>(
            pH, DIM, W1 + (size_t)l*DIM*MLPD, MLPD, b1 + (size_t)l*MLPD,
            pU, MLPD, NTOK, DIM);
        mma_gemm_kernel<2><<<dim3(DIM/BN, MT128), 256, GEMM_SMEM>>>(
            pU, MLPD, W2 + (size_t)l*MLPD*DIM, DIM, b2 + (size_t)l*DIM,
            pX, DIM, NTOK, MLPD);
    }

    head_kernel<<<BB, 256>>>(pX, Wh, bh, out);
}